// round 1
// baseline (speedup 1.0000x reference)
#include <cuda_runtime.h>

// Problem dims (fixed by the dataset)
#define B_DIM 128
#define T_DIM 100
#define N_DIM 1024            // I == O == 1024
#define MT    (B_DIM * T_DIM) // 12800 rows of the big GEMM
#define NTOT  (B_DIM * T_DIM * N_DIM)

// Scratch (static device globals — no runtime allocation allowed)
__device__ float g_H[(size_t)MT * N_DIM];      // 52.4 MB: h = x @ w
__device__ float g_M[(size_t)N_DIM * N_DIM];   // 4 MB:  (1-beta)*v - beta*(w^T w)
__device__ float g_invn[N_DIM];
__device__ int   g_cnt[T_DIM];                 // spikes per timestep (for loss/spread)

// ---------------------------------------------------------------------------
__global__ void zero_cnt_kernel() {
    if (threadIdx.x < T_DIM) g_cnt[threadIdx.x] = 0;
}

// inv_norm[o] = 1 / (sum_i w[i,o]^2 + eps)
__global__ void norm_kernel(const float* __restrict__ W) {
    int o = blockIdx.x * blockDim.x + threadIdx.x;
    float s = 0.f;
#pragma unroll 8
    for (int i = 0; i < N_DIM; i++) {
        float w = W[i * N_DIM + o];
        s += w * w;
    }
    g_invn[o] = 1.f / (s + 1e-8f);
}

// ---------------------------------------------------------------------------
// GEMM #1: H = X @ W   (X: [MT, 1024] row-major, W: [1024, 1024] row-major)
// 128x128 tile, BK=8, 256 threads, 8x8 per thread, fp32.
__global__ void __launch_bounds__(256) gemm_h_kernel(const float* __restrict__ A,
                                                     const float* __restrict__ B) {
    __shared__ float As[8][128];
    __shared__ float Bs[8][128];

    const int m0 = blockIdx.y * 128;
    const int n0 = blockIdx.x * 128;
    const int tid = threadIdx.x;

    // A tile load: 128 rows x 8 k -> one float4 per thread (transpose on store)
    const int a_row = tid >> 1;          // 0..127
    const int a_col = (tid & 1) * 4;     // 0 or 4
    // B tile load: 8 rows x 128 cols -> one float4 per thread
    const int b_row = tid >> 5;          // 0..7
    const int b_col = (tid & 31) * 4;    // 0..124

    const int tr = (tid >> 4) * 8;       // 0..120
    const int tc = (tid & 15) * 8;       // 0..120

    float acc[8][8];
#pragma unroll
    for (int i = 0; i < 8; i++)
#pragma unroll
        for (int j = 0; j < 8; j++) acc[i][j] = 0.f;

    for (int k0 = 0; k0 < N_DIM; k0 += 8) {
        float4 av = *(const float4*)&A[(size_t)(m0 + a_row) * N_DIM + k0 + a_col];
        float4 bv = *(const float4*)&B[(size_t)(k0 + b_row) * N_DIM + n0 + b_col];
        __syncthreads();
        As[a_col + 0][a_row] = av.x;
        As[a_col + 1][a_row] = av.y;
        As[a_col + 2][a_row] = av.z;
        As[a_col + 3][a_row] = av.w;
        *(float4*)&Bs[b_row][b_col] = bv;
        __syncthreads();
#pragma unroll
        for (int kk = 0; kk < 8; kk++) {
            float4 a0 = *(const float4*)&As[kk][tr];
            float4 a1 = *(const float4*)&As[kk][tr + 4];
            float4 b0 = *(const float4*)&Bs[kk][tc];
            float4 b1 = *(const float4*)&Bs[kk][tc + 4];
            float a[8] = {a0.x, a0.y, a0.z, a0.w, a1.x, a1.y, a1.z, a1.w};
            float b[8] = {b0.x, b0.y, b0.z, b0.w, b1.x, b1.y, b1.z, b1.w};
#pragma unroll
            for (int i = 0; i < 8; i++)
#pragma unroll
                for (int j = 0; j < 8; j++) acc[i][j] += a[i] * b[j];
        }
    }

#pragma unroll
    for (int i = 0; i < 8; i++) {
        float4 c0 = make_float4(acc[i][0], acc[i][1], acc[i][2], acc[i][3]);
        float4 c1 = make_float4(acc[i][4], acc[i][5], acc[i][6], acc[i][7]);
        *(float4*)&g_H[(size_t)(m0 + tr + i) * N_DIM + n0 + tc]     = c0;
        *(float4*)&g_H[(size_t)(m0 + tr + i) * N_DIM + n0 + tc + 4] = c1;
    }
}

// ---------------------------------------------------------------------------
// GEMM #2 (fused): M = (1-beta)*V - beta * (W^T W)
// d[m,n] = sum_k W[k,m]*W[k,n] -> both operands are k-major, no transpose needed.
__global__ void __launch_bounds__(256) gemm_dM_kernel(const float* __restrict__ W,
                                                      const float* __restrict__ V,
                                                      const float* __restrict__ beta_p) {
    __shared__ float As[8][128];
    __shared__ float Bs[8][128];

    const int m0 = blockIdx.y * 128;
    const int n0 = blockIdx.x * 128;
    const int tid = threadIdx.x;

    const int r = tid >> 5;           // 0..7  (k within tile)
    const int c = (tid & 31) * 4;     // 0..124

    const int tr = (tid >> 4) * 8;
    const int tc = (tid & 15) * 8;

    float acc[8][8];
#pragma unroll
    for (int i = 0; i < 8; i++)
#pragma unroll
        for (int j = 0; j < 8; j++) acc[i][j] = 0.f;

    for (int k0 = 0; k0 < N_DIM; k0 += 8) {
        float4 av = *(const float4*)&W[(size_t)(k0 + r) * N_DIM + m0 + c];
        float4 bv = *(const float4*)&W[(size_t)(k0 + r) * N_DIM + n0 + c];
        __syncthreads();
        *(float4*)&As[r][c] = av;
        *(float4*)&Bs[r][c] = bv;
        __syncthreads();
#pragma unroll
        for (int kk = 0; kk < 8; kk++) {
            float4 a0 = *(const float4*)&As[kk][tr];
            float4 a1 = *(const float4*)&As[kk][tr + 4];
            float4 b0 = *(const float4*)&Bs[kk][tc];
            float4 b1 = *(const float4*)&Bs[kk][tc + 4];
            float a[8] = {a0.x, a0.y, a0.z, a0.w, a1.x, a1.y, a1.z, a1.w};
            float b[8] = {b0.x, b0.y, b0.z, b0.w, b1.x, b1.y, b1.z, b1.w};
#pragma unroll
            for (int i = 0; i < 8; i++)
#pragma unroll
                for (int j = 0; j < 8; j++) acc[i][j] += a[i] * b[j];
        }
    }

    const float beta = beta_p[0];
    const float omb = 1.f - beta;
#pragma unroll
    for (int i = 0; i < 8; i++) {
        size_t row = (size_t)(m0 + tr + i) * N_DIM + n0 + tc;
        float4 v0 = *(const float4*)&V[row];
        float4 v1 = *(const float4*)&V[row + 4];
        float4 c0 = make_float4(omb * v0.x - beta * acc[i][0],
                                omb * v0.y - beta * acc[i][1],
                                omb * v0.z - beta * acc[i][2],
                                omb * v0.w - beta * acc[i][3]);
        float4 c1 = make_float4(omb * v1.x - beta * acc[i][4],
                                omb * v1.y - beta * acc[i][5],
                                omb * v1.z - beta * acc[i][6],
                                omb * v1.w - beta * acc[i][7]);
        *(float4*)&g_M[row]     = c0;
        *(float4*)&g_M[row + 4] = c1;
    }
}

// ---------------------------------------------------------------------------
// Scan: one block per batch element; thread o owns neuron o.
// spk @ M is done as a sparse row-gather over the (usually empty) fired set.
// Index compaction via ballot + prefix -> deterministic order.
__global__ void __launch_bounds__(1024) scan_kernel(const float* __restrict__ bvec,
                                                    const float* __restrict__ beta_p,
                                                    float* __restrict__ out) {
    __shared__ int sidx[N_DIM];
    __shared__ int warp_cnt[32];
    __shared__ int warp_off[32];
    __shared__ int scnt;

    const int b = blockIdx.x;
    const int o = threadIdx.x;
    const int lane = o & 31;
    const int warp = o >> 5;

    const float beta = beta_p[0];
    const float omb = 1.f - beta;
    const float inv_n = g_invn[o];
    const float bth = bvec[o];

    float mem = 0.f;
    int K = 0;

    const float* Hrow = g_H + (size_t)b * T_DIM * N_DIM;
    float* Orow = out + (size_t)b * T_DIM * N_DIM;

    for (int t = 0; t < T_DIM; t++) {
        float h = Hrow[(size_t)t * N_DIM + o];   // issue load early
        float acc = 0.f;
        for (int k = 0; k < K; k++) acc += g_M[(size_t)sidx[k] * N_DIM + o];

        mem = mem * beta + h * omb + acc;
        float s = (mem * inv_n - bth > 0.f) ? 1.f : 0.f;
        Orow[(size_t)t * N_DIM + o] = s;

        unsigned bal = __ballot_sync(0xffffffffu, s > 0.f);
        __syncthreads();                          // all sidx reads done
        if (lane == 0) warp_cnt[warp] = __popc(bal);
        __syncthreads();
        if (o == 0) {
            int run = 0;
#pragma unroll
            for (int w = 0; w < 32; w++) { warp_off[w] = run; run += warp_cnt[w]; }
            scnt = run;
            if (run > 0) atomicAdd(&g_cnt[t], run);
        }
        __syncthreads();
        if (s > 0.f)
            sidx[warp_off[warp] + __popc(bal & ((1u << lane) - 1u))] = o;
        K = scnt;
        __syncthreads();                          // sidx writes visible next iter
    }
}

// loss = 0.5*mean(spk^2) = 0.5*n_spikes/NTOT ; spread = max_t count_t / (B*O)
__global__ void finalize_kernel(float* __restrict__ out, int out_size) {
    if (threadIdx.x == 0 && out_size >= NTOT + 2) {
        int sum = 0, mx = 0;
        for (int t = 0; t < T_DIM; t++) {
            sum += g_cnt[t];
            mx = max(mx, g_cnt[t]);
        }
        out[NTOT]     = 0.5f * (float)sum / (float)NTOT;
        out[NTOT + 1] = (float)mx / (float)(B_DIM * N_DIM);
    }
}

// ---------------------------------------------------------------------------
extern "C" void kernel_launch(void* const* d_in, const int* in_sizes, int n_in,
                              void* d_out, int out_size) {
    const float* x    = (const float*)d_in[0];   // [128,100,1024]
    const float* w    = (const float*)d_in[1];   // [1024,1024]
    const float* v    = (const float*)d_in[2];   // [1024,1024]
    const float* beta = (const float*)d_in[3];   // [1]
    const float* bvec = (const float*)d_in[4];   // [1024]
    float* out = (float*)d_out;

    zero_cnt_kernel<<<1, 128>>>();
    norm_kernel<<<N_DIM / 256, 256>>>(w);
    gemm_dM_kernel<<<dim3(N_DIM / 128, N_DIM / 128), 256>>>(w, v, beta);
    gemm_h_kernel<<<dim3(N_DIM / 128, MT / 128), 256>>>(x, w);
    scan_kernel<<<B_DIM, 1024>>>(bvec, beta, out);
    finalize_kernel<<<1, 32>>>(out, out_size);
}

// round 3
// speedup vs baseline: 1.7527x; 1.7527x over previous
#include <cuda_runtime.h>
#include <cuda_bf16.h>
#include <cstdint>

#define B_DIM 128
#define T_DIM 100
#define N_DIM 1024
#define MT    (B_DIM * T_DIM)
#define NTOT  (B_DIM * T_DIM * N_DIM)

// ------------------------- device scratch (no runtime alloc) ----------------
__device__ float g_H[(size_t)MT * N_DIM];       // 52.4 MB fp32 h = x@w
__device__ float g_M[(size_t)N_DIM * N_DIM];    // (1-b)*v - b*(w^T w)
__device__ float g_invn[N_DIM];
__device__ int   g_cnt[T_DIM];
__device__ __nv_bfloat16 g_Xhi[(size_t)MT * N_DIM];
__device__ __nv_bfloat16 g_Xlo[(size_t)MT * N_DIM];
__device__ __nv_bfloat16 g_Wthi[(size_t)N_DIM * N_DIM]; // W^T [n][k]
__device__ __nv_bfloat16 g_Wtlo[(size_t)N_DIM * N_DIM];

// ------------------------- helpers ------------------------------------------
__device__ __forceinline__ uint32_t smem_u32(const void* p) {
    uint32_t a;
    asm("{ .reg .u64 t; cvta.to.shared.u64 t, %1; cvt.u32.u64 %0, t; }" : "=r"(a) : "l"(p));
    return a;
}
#define CP_ASYNC16(dst, src) \
    asm volatile("cp.async.cg.shared.global [%0], [%1], 16;" :: "r"(dst), "l"(src) : "memory")
#define CP_COMMIT() asm volatile("cp.async.commit_group;" ::: "memory")

__device__ __forceinline__ void ldsm4(uint32_t* r, uint32_t addr) {
    asm volatile("ldmatrix.sync.aligned.m8n8.x4.shared.b16 {%0,%1,%2,%3}, [%4];"
                 : "=r"(r[0]), "=r"(r[1]), "=r"(r[2]), "=r"(r[3]) : "r"(addr));
}
__device__ __forceinline__ void mma16816(float* c, const uint32_t* a, const uint32_t* b) {
    asm volatile("mma.sync.aligned.m16n8k16.row.col.f32.bf16.bf16.f32 "
                 "{%0,%1,%2,%3}, {%4,%5,%6,%7}, {%8,%9}, {%0,%1,%2,%3};"
                 : "+f"(c[0]), "+f"(c[1]), "+f"(c[2]), "+f"(c[3])
                 : "r"(a[0]), "r"(a[1]), "r"(a[2]), "r"(a[3]), "r"(b[0]), "r"(b[1]));
}

// ------------------------- small kernels ------------------------------------
__global__ void zero_cnt_kernel() {
    if (threadIdx.x < T_DIM) g_cnt[threadIdx.x] = 0;
}

__global__ void norm_kernel(const float* __restrict__ W) {
    int o = blockIdx.x * blockDim.x + threadIdx.x;
    float s = 0.f;
#pragma unroll 8
    for (int i = 0; i < N_DIM; i++) {
        float w = W[i * N_DIM + o];
        s += w * w;
    }
    g_invn[o] = 1.f / (s + 1e-8f);
}

__global__ void convert_x_kernel(const float* __restrict__ x) {
    size_t i = (size_t)blockIdx.x * blockDim.x + threadIdx.x;   // over NTOT/4
    float4 v = ((const float4*)x)[i];
    __nv_bfloat16 h0 = __float2bfloat16(v.x), h1 = __float2bfloat16(v.y);
    __nv_bfloat16 h2 = __float2bfloat16(v.z), h3 = __float2bfloat16(v.w);
    __nv_bfloat16 l0 = __float2bfloat16(v.x - __bfloat162float(h0));
    __nv_bfloat16 l1 = __float2bfloat16(v.y - __bfloat162float(h1));
    __nv_bfloat16 l2 = __float2bfloat16(v.z - __bfloat162float(h2));
    __nv_bfloat16 l3 = __float2bfloat16(v.w - __bfloat162float(h3));
    ((__nv_bfloat162*)g_Xhi)[i * 2]     = __nv_bfloat162(h0, h1);
    ((__nv_bfloat162*)g_Xhi)[i * 2 + 1] = __nv_bfloat162(h2, h3);
    ((__nv_bfloat162*)g_Xlo)[i * 2]     = __nv_bfloat162(l0, l1);
    ((__nv_bfloat162*)g_Xlo)[i * 2 + 1] = __nv_bfloat162(l2, l3);
}

__global__ void convert_wt_kernel(const float* __restrict__ W) {
    __shared__ float tile[32][33];
    int n0 = blockIdx.x * 32, k0 = blockIdx.y * 32;
    int tx = threadIdx.x, ty = threadIdx.y;
    tile[ty][tx] = W[(size_t)(k0 + ty) * N_DIM + n0 + tx];
    __syncthreads();
    float v = tile[tx][ty];                 // = W[k0+tx][n0+ty]
    __nv_bfloat16 h = __float2bfloat16(v);
    __nv_bfloat16 l = __float2bfloat16(v - __bfloat162float(h));
    size_t dst = (size_t)(n0 + ty) * N_DIM + k0 + tx;
    g_Wthi[dst] = h;
    g_Wtlo[dst] = l;
}

// ------------------------- HMMA GEMM: H = X @ W (3-pass split bf16) ---------
// 128x128 CTA tile, BK=64, 8 warps (4m x 2n), warp tile 32x64.
// smem per stage: Ahi/Alo/Bhi/Blo, each 128 rows x 128 B (SW128-swizzled).
#define OF_AHI 0
#define OF_ALO 16384
#define OF_BHI 32768
#define OF_BLO 49152
#define STAGE  65536
#define SMEM_BYTES (2 * STAGE)

__global__ void __launch_bounds__(256) gemm_h_tc_kernel() {
    extern __shared__ char smem[];
    const uint32_t sbase = smem_u32(smem);
    const int tid  = threadIdx.x;
    const int lane = tid & 31;
    const int wid  = tid >> 5;
    const int wm   = wid & 3;        // warp m index (0..3) -> rows wm*32..+31
    const int wn   = wid >> 2;       // warp n index (0..1) -> cols wn*64..+63
    const int m0 = blockIdx.y * 128;
    const int n0 = blockIdx.x * 128;

    // per-thread cp.async source/dst components (16 chunks of 16B per thread)
    // c = tid + i*256 ; t = tile id ; row/cc within tile
    // ldmatrix per-lane components
    const int a_r   = lane & 15;          // A row within 16-row tile
    const int a_k16 = (lane >> 4) * 16;   // A byte offset: k half (0/8 halves)
    const int b_r   = ((lane >> 4) << 3) + (lane & 7);  // B row within 16-n tile
    const int b_k16 = ((lane >> 3) & 1) * 16;           // B byte offset: k half

    float c[2][8][4];
#pragma unroll
    for (int mt = 0; mt < 2; mt++)
#pragma unroll
        for (int nt = 0; nt < 8; nt++)
#pragma unroll
            for (int q = 0; q < 4; q++) c[mt][nt][q] = 0.f;

    // ---- async load of one K-chunk (64 columns) into a stage buffer ----
    auto load_chunk = [&](int it, uint32_t bufofs) {
        const int k0 = it * 64;
#pragma unroll
        for (int i = 0; i < 16; i++) {
            int cix = tid + i * 256;
            int t = cix >> 10;
            int wi = cix & 1023;
            int row = wi >> 3;
            int cc = wi & 7;
            uint32_t off = row * 128 + cc * 16;
            uint32_t sw = off ^ ((off >> 3) & 0x70);
            const __nv_bfloat16* src;
            uint32_t soff;
            if (t == 0)      { src = g_Xhi  + (size_t)(m0 + row) * N_DIM + k0 + cc * 8; soff = OF_AHI; }
            else if (t == 1) { src = g_Xlo  + (size_t)(m0 + row) * N_DIM + k0 + cc * 8; soff = OF_ALO; }
            else if (t == 2) { src = g_Wthi + (size_t)(n0 + row) * N_DIM + k0 + cc * 8; soff = OF_BHI; }
            else             { src = g_Wtlo + (size_t)(n0 + row) * N_DIM + k0 + cc * 8; soff = OF_BLO; }
            CP_ASYNC16(sbase + bufofs + soff + sw, src);
        }
    };

    load_chunk(0, 0);
    CP_COMMIT();

    for (int it = 0; it < 16; it++) {
        const uint32_t buf = (it & 1) ? STAGE : 0;
        if (it + 1 < 16) {
            load_chunk(it + 1, (it & 1) ? 0 : STAGE);
            CP_COMMIT();
            asm volatile("cp.async.wait_group 1;" ::: "memory");
        } else {
            asm volatile("cp.async.wait_group 0;" ::: "memory");
        }
        __syncthreads();

        const uint32_t bb = sbase + buf;
#pragma unroll
        for (int ks = 0; ks < 4; ks++) {
            // A fragments (2 m-tiles, hi+lo)
            uint32_t ahi[2][4], alo[2][4];
#pragma unroll
            for (int mt = 0; mt < 2; mt++) {
                uint32_t row = wm * 32 + mt * 16 + a_r;
                uint32_t off = row * 128 + ks * 32 + a_k16;
                uint32_t sw = off ^ ((off >> 3) & 0x70);
                ldsm4(ahi[mt], bb + OF_AHI + sw);
                ldsm4(alo[mt], bb + OF_ALO + sw);
            }
#pragma unroll
            for (int nt = 0; nt < 4; nt++) {       // 16 n-cols per iter
                uint32_t bhi[4], blo[4];
                uint32_t row = wn * 64 + nt * 16 + b_r;
                uint32_t off = row * 128 + ks * 32 + b_k16;
                uint32_t sw = off ^ ((off >> 3) & 0x70);
                ldsm4(bhi, bb + OF_BHI + sw);
                ldsm4(blo, bb + OF_BLO + sw);
#pragma unroll
                for (int mt = 0; mt < 2; mt++) {
                    mma16816(c[mt][nt * 2],     ahi[mt], bhi);
                    mma16816(c[mt][nt * 2],     ahi[mt], blo);
                    mma16816(c[mt][nt * 2],     alo[mt], bhi);
                    mma16816(c[mt][nt * 2 + 1], ahi[mt], bhi + 2);
                    mma16816(c[mt][nt * 2 + 1], ahi[mt], blo + 2);
                    mma16816(c[mt][nt * 2 + 1], alo[mt], bhi + 2);
                }
            }
        }
        __syncthreads();
    }

    // ---- epilogue: fragment stores (float2 per pair) ----
    const int g  = lane >> 2;
    const int tg = lane & 3;
#pragma unroll
    for (int mt = 0; mt < 2; mt++) {
        int row0 = m0 + wm * 32 + mt * 16 + g;
#pragma unroll
        for (int nt = 0; nt < 8; nt++) {
            int col = n0 + wn * 64 + nt * 8 + tg * 2;
            *(float2*)&g_H[(size_t)row0 * N_DIM + col] =
                make_float2(c[mt][nt][0], c[mt][nt][1]);
            *(float2*)&g_H[(size_t)(row0 + 8) * N_DIM + col] =
                make_float2(c[mt][nt][2], c[mt][nt][3]);
        }
    }
}

// ------------------------- M = (1-beta)*V - beta*(W^T W)  (SIMT fp32) -------
__global__ void __launch_bounds__(256) gemm_dM_kernel(const float* __restrict__ W,
                                                      const float* __restrict__ V,
                                                      const float* __restrict__ beta_p) {
    __shared__ float As[8][128];
    __shared__ float Bs[8][128];

    const int m0 = blockIdx.y * 128;
    const int n0 = blockIdx.x * 128;
    const int tid = threadIdx.x;
    const int r = tid >> 5;
    const int c = (tid & 31) * 4;
    const int tr = (tid >> 4) * 8;
    const int tc = (tid & 15) * 8;

    float acc[8][8];
#pragma unroll
    for (int i = 0; i < 8; i++)
#pragma unroll
        for (int j = 0; j < 8; j++) acc[i][j] = 0.f;

    for (int k0 = 0; k0 < N_DIM; k0 += 8) {
        float4 av = *(const float4*)&W[(size_t)(k0 + r) * N_DIM + m0 + c];
        float4 bv = *(const float4*)&W[(size_t)(k0 + r) * N_DIM + n0 + c];
        __syncthreads();
        *(float4*)&As[r][c] = av;
        *(float4*)&Bs[r][c] = bv;
        __syncthreads();
#pragma unroll
        for (int kk = 0; kk < 8; kk++) {
            float4 a0 = *(const float4*)&As[kk][tr];
            float4 a1 = *(const float4*)&As[kk][tr + 4];
            float4 b0 = *(const float4*)&Bs[kk][tc];
            float4 b1 = *(const float4*)&Bs[kk][tc + 4];
            float a[8] = {a0.x, a0.y, a0.z, a0.w, a1.x, a1.y, a1.z, a1.w};
            float b[8] = {b0.x, b0.y, b0.z, b0.w, b1.x, b1.y, b1.z, b1.w};
#pragma unroll
            for (int i = 0; i < 8; i++)
#pragma unroll
                for (int j = 0; j < 8; j++) acc[i][j] += a[i] * b[j];
        }
    }

    const float beta = beta_p[0];
    const float omb = 1.f - beta;
#pragma unroll
    for (int i = 0; i < 8; i++) {
        size_t row = (size_t)(m0 + tr + i) * N_DIM + n0 + tc;
        float4 v0 = *(const float4*)&V[row];
        float4 v1 = *(const float4*)&V[row + 4];
        float4 c0 = make_float4(omb * v0.x - beta * acc[i][0], omb * v0.y - beta * acc[i][1],
                                omb * v0.z - beta * acc[i][2], omb * v0.w - beta * acc[i][3]);
        float4 c1 = make_float4(omb * v1.x - beta * acc[i][4], omb * v1.y - beta * acc[i][5],
                                omb * v1.z - beta * acc[i][6], omb * v1.w - beta * acc[i][7]);
        *(float4*)&g_M[row]     = c0;
        *(float4*)&g_M[row + 4] = c1;
    }
}

// ------------------------- scan (unchanged, known-correct) ------------------
__global__ void __launch_bounds__(1024) scan_kernel(const float* __restrict__ bvec,
                                                    const float* __restrict__ beta_p,
                                                    float* __restrict__ out) {
    __shared__ int sidx[N_DIM];
    __shared__ int warp_cnt[32];
    __shared__ int warp_off[32];
    __shared__ int scnt;

    const int b = blockIdx.x;
    const int o = threadIdx.x;
    const int lane = o & 31;
    const int warp = o >> 5;

    const float beta = beta_p[0];
    const float omb = 1.f - beta;
    const float inv_n = g_invn[o];
    const float bth = bvec[o];

    float mem = 0.f;
    int K = 0;

    const float* Hrow = g_H + (size_t)b * T_DIM * N_DIM;
    float* Orow = out + (size_t)b * T_DIM * N_DIM;

    for (int t = 0; t < T_DIM; t++) {
        float h = Hrow[(size_t)t * N_DIM + o];
        float acc = 0.f;
        for (int k = 0; k < K; k++) acc += g_M[(size_t)sidx[k] * N_DIM + o];

        mem = mem * beta + h * omb + acc;
        float s = (mem * inv_n - bth > 0.f) ? 1.f : 0.f;
        Orow[(size_t)t * N_DIM + o] = s;

        unsigned bal = __ballot_sync(0xffffffffu, s > 0.f);
        __syncthreads();
        if (lane == 0) warp_cnt[warp] = __popc(bal);
        __syncthreads();
        if (o == 0) {
            int run = 0;
#pragma unroll
            for (int w = 0; w < 32; w++) { warp_off[w] = run; run += warp_cnt[w]; }
            scnt = run;
            if (run > 0) atomicAdd(&g_cnt[t], run);
        }
        __syncthreads();
        if (s > 0.f)
            sidx[warp_off[warp] + __popc(bal & ((1u << lane) - 1u))] = o;
        K = scnt;
        __syncthreads();
    }
}

__global__ void finalize_kernel(float* __restrict__ out, int out_size) {
    if (threadIdx.x == 0 && out_size >= NTOT + 2) {
        int sum = 0, mx = 0;
        for (int t = 0; t < T_DIM; t++) {
            sum += g_cnt[t];
            mx = max(mx, g_cnt[t]);
        }
        out[NTOT]     = 0.5f * (float)sum / (float)NTOT;
        out[NTOT + 1] = (float)mx / (float)(B_DIM * N_DIM);
    }
}

// ---------------------------------------------------------------------------
extern "C" void kernel_launch(void* const* d_in, const int* in_sizes, int n_in,
                              void* d_out, int out_size) {
    const float* x    = (const float*)d_in[0];
    const float* w    = (const float*)d_in[1];
    const float* v    = (const float*)d_in[2];
    const float* beta = (const float*)d_in[3];
    const float* bvec = (const float*)d_in[4];
    float* out = (float*)d_out;

    cudaFuncSetAttribute(gemm_h_tc_kernel,
                         cudaFuncAttributeMaxDynamicSharedMemorySize, SMEM_BYTES);

    zero_cnt_kernel<<<1, 128>>>();
    norm_kernel<<<N_DIM / 256, 256>>>(w);
    convert_x_kernel<<<NTOT / 4 / 256, 256>>>(x);
    convert_wt_kernel<<<dim3(N_DIM / 32, N_DIM / 32), dim3(32, 32)>>>(w);
    gemm_dM_kernel<<<dim3(N_DIM / 128, N_DIM / 128), 256>>>(w, v, beta);
    gemm_h_tc_kernel<<<dim3(N_DIM / 128, MT / 128), 256, SMEM_BYTES>>>();
    scan_kernel<<<B_DIM, 1024>>>(bvec, beta, out);
    finalize_kernel<<<1, 32>>>(out, out_size);
}

// round 4
// speedup vs baseline: 2.3162x; 1.3215x over previous
#include <cuda_runtime.h>
#include <cuda_bf16.h>
#include <cstdint>

#define B_DIM 128
#define T_DIM 100
#define N_DIM 1024
#define MT    (B_DIM * T_DIM)
#define NTOT  (B_DIM * T_DIM * N_DIM)

// ------------------------- device scratch (no runtime alloc) ----------------
__device__ float g_H[(size_t)MT * N_DIM];       // 52.4 MB fp32 h = x@w
__device__ float g_M[(size_t)N_DIM * N_DIM];    // (1-b)*v - b*(w^T w)
__device__ float g_invn[N_DIM];
__device__ int   g_cnt[T_DIM];
__device__ __nv_bfloat16 g_Xhi[(size_t)MT * N_DIM];
__device__ __nv_bfloat16 g_Xlo[(size_t)MT * N_DIM];
__device__ __nv_bfloat16 g_Wthi[(size_t)N_DIM * N_DIM]; // W^T [n][k]
__device__ __nv_bfloat16 g_Wtlo[(size_t)N_DIM * N_DIM];

// ------------------------- helpers ------------------------------------------
__device__ __forceinline__ uint32_t smem_u32(const void* p) {
    uint32_t a;
    asm("{ .reg .u64 t; cvta.to.shared.u64 t, %1; cvt.u32.u64 %0, t; }" : "=r"(a) : "l"(p));
    return a;
}
#define CP_ASYNC16(dst, src) \
    asm volatile("cp.async.cg.shared.global [%0], [%1], 16;" :: "r"(dst), "l"(src) : "memory")
#define CP_COMMIT() asm volatile("cp.async.commit_group;" ::: "memory")

__device__ __forceinline__ void ldsm4(uint32_t* r, uint32_t addr) {
    asm volatile("ldmatrix.sync.aligned.m8n8.x4.shared.b16 {%0,%1,%2,%3}, [%4];"
                 : "=r"(r[0]), "=r"(r[1]), "=r"(r[2]), "=r"(r[3]) : "r"(addr));
}
__device__ __forceinline__ void mma16816(float* c, const uint32_t* a, const uint32_t* b) {
    asm volatile("mma.sync.aligned.m16n8k16.row.col.f32.bf16.bf16.f32 "
                 "{%0,%1,%2,%3}, {%4,%5,%6,%7}, {%8,%9}, {%0,%1,%2,%3};"
                 : "+f"(c[0]), "+f"(c[1]), "+f"(c[2]), "+f"(c[3])
                 : "r"(a[0]), "r"(a[1]), "r"(a[2]), "r"(a[3]), "r"(b[0]), "r"(b[1]));
}

// ------------------------- small kernels ------------------------------------
__global__ void zero_cnt_kernel() {
    if (threadIdx.x < T_DIM) g_cnt[threadIdx.x] = 0;
}

__global__ void norm_kernel(const float* __restrict__ W) {
    int o = blockIdx.x * blockDim.x + threadIdx.x;
    float s = 0.f;
#pragma unroll 8
    for (int i = 0; i < N_DIM; i++) {
        float w = W[i * N_DIM + o];
        s += w * w;
    }
    g_invn[o] = 1.f / (s + 1e-8f);
}

__global__ void convert_x_kernel(const float* __restrict__ x) {
    size_t i = (size_t)blockIdx.x * blockDim.x + threadIdx.x;   // over NTOT/4
    float4 v = ((const float4*)x)[i];
    __nv_bfloat16 h0 = __float2bfloat16(v.x), h1 = __float2bfloat16(v.y);
    __nv_bfloat16 h2 = __float2bfloat16(v.z), h3 = __float2bfloat16(v.w);
    __nv_bfloat16 l0 = __float2bfloat16(v.x - __bfloat162float(h0));
    __nv_bfloat16 l1 = __float2bfloat16(v.y - __bfloat162float(h1));
    __nv_bfloat16 l2 = __float2bfloat16(v.z - __bfloat162float(h2));
    __nv_bfloat16 l3 = __float2bfloat16(v.w - __bfloat162float(h3));
    ((__nv_bfloat162*)g_Xhi)[i * 2]     = __nv_bfloat162(h0, h1);
    ((__nv_bfloat162*)g_Xhi)[i * 2 + 1] = __nv_bfloat162(h2, h3);
    ((__nv_bfloat162*)g_Xlo)[i * 2]     = __nv_bfloat162(l0, l1);
    ((__nv_bfloat162*)g_Xlo)[i * 2 + 1] = __nv_bfloat162(l2, l3);
}

__global__ void convert_wt_kernel(const float* __restrict__ W) {
    __shared__ float tile[32][33];
    int n0 = blockIdx.x * 32, k0 = blockIdx.y * 32;
    int tx = threadIdx.x, ty = threadIdx.y;
    tile[ty][tx] = W[(size_t)(k0 + ty) * N_DIM + n0 + tx];
    __syncthreads();
    float v = tile[tx][ty];                 // = W[k0+tx][n0+ty]
    __nv_bfloat16 h = __float2bfloat16(v);
    __nv_bfloat16 l = __float2bfloat16(v - __bfloat162float(h));
    size_t dst = (size_t)(n0 + ty) * N_DIM + k0 + tx;
    g_Wthi[dst] = h;
    g_Wtlo[dst] = l;
}

// ------------------------- HMMA GEMM common pieces --------------------------
// 128x128 CTA tile, BK=64, 8 warps (4m x 2n), warp tile 32x64.
// smem per stage: Ahi/Alo/Bhi/Blo, each 128 rows x 128 B (SW128-swizzled).
#define OF_AHI 0
#define OF_ALO 16384
#define OF_BHI 32768
#define OF_BLO 49152
#define STAGE  65536
#define SMEM_BYTES (2 * STAGE)

struct Frag { float c[2][8][4]; };

// Compute one K-chunk (64 k) worth of MMAs from a stage buffer.
// Passes are grouped so accumulator RAW chains have distance 16.
__device__ __forceinline__ void mma_chunk(Frag& f, uint32_t bb, int wm, int wn, int lane) {
    const int a_r   = lane & 15;
    const int a_k16 = (lane >> 4) * 16;
    const int b_r   = ((lane >> 4) << 3) + (lane & 7);
    const int b_k16 = ((lane >> 3) & 1) * 16;
#pragma unroll
    for (int ks = 0; ks < 4; ks++) {
        uint32_t ahi[2][4], alo[2][4], bhi[4][4], blo[4][4];
#pragma unroll
        for (int mt = 0; mt < 2; mt++) {
            uint32_t row = wm * 32 + mt * 16 + a_r;
            uint32_t off = row * 128 + ks * 32 + a_k16;
            uint32_t sw = off ^ ((off >> 3) & 0x70);
            ldsm4(ahi[mt], bb + OF_AHI + sw);
            ldsm4(alo[mt], bb + OF_ALO + sw);
        }
#pragma unroll
        for (int nt = 0; nt < 4; nt++) {
            uint32_t row = wn * 64 + nt * 16 + b_r;
            uint32_t off = row * 128 + ks * 32 + b_k16;
            uint32_t sw = off ^ ((off >> 3) & 0x70);
            ldsm4(bhi[nt], bb + OF_BHI + sw);
            ldsm4(blo[nt], bb + OF_BLO + sw);
        }
        // pass 1: ahi x bhi (16 independent MMAs)
#pragma unroll
        for (int nt = 0; nt < 4; nt++)
#pragma unroll
            for (int mt = 0; mt < 2; mt++) {
                mma16816(f.c[mt][nt * 2],     ahi[mt], bhi[nt]);
                mma16816(f.c[mt][nt * 2 + 1], ahi[mt], bhi[nt] + 2);
            }
        // pass 2: ahi x blo
#pragma unroll
        for (int nt = 0; nt < 4; nt++)
#pragma unroll
            for (int mt = 0; mt < 2; mt++) {
                mma16816(f.c[mt][nt * 2],     ahi[mt], blo[nt]);
                mma16816(f.c[mt][nt * 2 + 1], ahi[mt], blo[nt] + 2);
            }
        // pass 3: alo x bhi
#pragma unroll
        for (int nt = 0; nt < 4; nt++)
#pragma unroll
            for (int mt = 0; mt < 2; mt++) {
                mma16816(f.c[mt][nt * 2],     alo[mt], bhi[nt]);
                mma16816(f.c[mt][nt * 2 + 1], alo[mt], bhi[nt] + 2);
            }
    }
}

// ------------------------- GEMM #1: H = X @ W -------------------------------
__global__ void __launch_bounds__(256) gemm_h_tc_kernel() {
    extern __shared__ char smem[];
    const uint32_t sbase = smem_u32(smem);
    const int tid  = threadIdx.x;
    const int lane = tid & 31;
    const int wid  = tid >> 5;
    const int wm   = wid & 3;
    const int wn   = wid >> 2;
    const int m0 = blockIdx.y * 128;
    const int n0 = blockIdx.x * 128;

    Frag f;
#pragma unroll
    for (int mt = 0; mt < 2; mt++)
#pragma unroll
        for (int nt = 0; nt < 8; nt++)
#pragma unroll
            for (int q = 0; q < 4; q++) f.c[mt][nt][q] = 0.f;

    auto load_chunk = [&](int it, uint32_t bufofs) {
        const int k0 = it * 64;
#pragma unroll
        for (int i = 0; i < 16; i++) {
            int cix = tid + i * 256;
            int t = cix >> 10;
            int wi = cix & 1023;
            int row = wi >> 3;
            int cc = wi & 7;
            uint32_t off = row * 128 + cc * 16;
            uint32_t sw = off ^ ((off >> 3) & 0x70);
            const __nv_bfloat16* src;
            uint32_t soff;
            if (t == 0)      { src = g_Xhi  + (size_t)(m0 + row) * N_DIM + k0 + cc * 8; soff = OF_AHI; }
            else if (t == 1) { src = g_Xlo  + (size_t)(m0 + row) * N_DIM + k0 + cc * 8; soff = OF_ALO; }
            else if (t == 2) { src = g_Wthi + (size_t)(n0 + row) * N_DIM + k0 + cc * 8; soff = OF_BHI; }
            else             { src = g_Wtlo + (size_t)(n0 + row) * N_DIM + k0 + cc * 8; soff = OF_BLO; }
            CP_ASYNC16(sbase + bufofs + soff + sw, src);
        }
    };

    load_chunk(0, 0);
    CP_COMMIT();

    for (int it = 0; it < 16; it++) {
        const uint32_t buf = (it & 1) ? STAGE : 0;
        if (it + 1 < 16) {
            load_chunk(it + 1, (it & 1) ? 0 : STAGE);
            CP_COMMIT();
            asm volatile("cp.async.wait_group 1;" ::: "memory");
        } else {
            asm volatile("cp.async.wait_group 0;" ::: "memory");
        }
        __syncthreads();
        mma_chunk(f, sbase + buf, wm, wn, lane);
        __syncthreads();
    }

    const int g  = lane >> 2;
    const int tg = lane & 3;
#pragma unroll
    for (int mt = 0; mt < 2; mt++) {
        int row0 = m0 + wm * 32 + mt * 16 + g;
#pragma unroll
        for (int nt = 0; nt < 8; nt++) {
            int col = n0 + wn * 64 + nt * 8 + tg * 2;
            *(float2*)&g_H[(size_t)row0 * N_DIM + col] =
                make_float2(f.c[mt][nt][0], f.c[mt][nt][1]);
            *(float2*)&g_H[(size_t)(row0 + 8) * N_DIM + col] =
                make_float2(f.c[mt][nt][2], f.c[mt][nt][3]);
        }
    }
}

// ------------------------- GEMM #2: M = (1-b)*V - b*(W^T W) -----------------
// d[m,n] = sum_k Wt[m,k]*Wt[n,k]; A and B tiles both come from g_Wt{hi,lo}.
__global__ void __launch_bounds__(256) gemm_dM_tc_kernel(const float* __restrict__ V,
                                                         const float* __restrict__ beta_p) {
    extern __shared__ char smem[];
    const uint32_t sbase = smem_u32(smem);
    const int tid  = threadIdx.x;
    const int lane = tid & 31;
    const int wid  = tid >> 5;
    const int wm   = wid & 3;
    const int wn   = wid >> 2;
    const int m0 = blockIdx.y * 128;
    const int n0 = blockIdx.x * 128;

    Frag f;
#pragma unroll
    for (int mt = 0; mt < 2; mt++)
#pragma unroll
        for (int nt = 0; nt < 8; nt++)
#pragma unroll
            for (int q = 0; q < 4; q++) f.c[mt][nt][q] = 0.f;

    auto load_chunk = [&](int it, uint32_t bufofs) {
        const int k0 = it * 64;
#pragma unroll
        for (int i = 0; i < 16; i++) {
            int cix = tid + i * 256;
            int t = cix >> 10;
            int wi = cix & 1023;
            int row = wi >> 3;
            int cc = wi & 7;
            uint32_t off = row * 128 + cc * 16;
            uint32_t sw = off ^ ((off >> 3) & 0x70);
            const __nv_bfloat16* src;
            uint32_t soff;
            if (t == 0)      { src = g_Wthi + (size_t)(m0 + row) * N_DIM + k0 + cc * 8; soff = OF_AHI; }
            else if (t == 1) { src = g_Wtlo + (size_t)(m0 + row) * N_DIM + k0 + cc * 8; soff = OF_ALO; }
            else if (t == 2) { src = g_Wthi + (size_t)(n0 + row) * N_DIM + k0 + cc * 8; soff = OF_BHI; }
            else             { src = g_Wtlo + (size_t)(n0 + row) * N_DIM + k0 + cc * 8; soff = OF_BLO; }
            CP_ASYNC16(sbase + bufofs + soff + sw, src);
        }
    };

    load_chunk(0, 0);
    CP_COMMIT();

    for (int it = 0; it < 16; it++) {
        const uint32_t buf = (it & 1) ? STAGE : 0;
        if (it + 1 < 16) {
            load_chunk(it + 1, (it & 1) ? 0 : STAGE);
            CP_COMMIT();
            asm volatile("cp.async.wait_group 1;" ::: "memory");
        } else {
            asm volatile("cp.async.wait_group 0;" ::: "memory");
        }
        __syncthreads();
        mma_chunk(f, sbase + buf, wm, wn, lane);
        __syncthreads();
    }

    const float beta = beta_p[0];
    const float omb = 1.f - beta;
    const int g  = lane >> 2;
    const int tg = lane & 3;
#pragma unroll
    for (int mt = 0; mt < 2; mt++) {
        int row0 = m0 + wm * 32 + mt * 16 + g;
#pragma unroll
        for (int nt = 0; nt < 8; nt++) {
            int col = n0 + wn * 64 + nt * 8 + tg * 2;
            size_t i0 = (size_t)row0 * N_DIM + col;
            size_t i1 = (size_t)(row0 + 8) * N_DIM + col;
            float2 v0 = *(const float2*)&V[i0];
            float2 v1 = *(const float2*)&V[i1];
            *(float2*)&g_M[i0] = make_float2(omb * v0.x - beta * f.c[mt][nt][0],
                                             omb * v0.y - beta * f.c[mt][nt][1]);
            *(float2*)&g_M[i1] = make_float2(omb * v1.x - beta * f.c[mt][nt][2],
                                             omb * v1.y - beta * f.c[mt][nt][3]);
        }
    }
}

// ------------------------- scan ---------------------------------------------
__global__ void __launch_bounds__(1024) scan_kernel(const float* __restrict__ bvec,
                                                    const float* __restrict__ beta_p,
                                                    float* __restrict__ out) {
    __shared__ int sidx[N_DIM];
    __shared__ int warp_cnt[32];
    __shared__ int warp_off[32];
    __shared__ int scnt;

    const int b = blockIdx.x;
    const int o = threadIdx.x;
    const int lane = o & 31;
    const int warp = o >> 5;

    const float beta = beta_p[0];
    const float omb = 1.f - beta;
    const float inv_n = g_invn[o];
    const float bth = bvec[o];

    float mem = 0.f;
    int K = 0;

    const float* Hrow = g_H + (size_t)b * T_DIM * N_DIM;
    float* Orow = out + (size_t)b * T_DIM * N_DIM;

    // depth-2 software pipeline on the h loads
    float h0 = Hrow[o];
    float h1 = Hrow[N_DIM + o];

    for (int t = 0; t < T_DIM; t++) {
        float h = h0;
        h0 = h1;
        if (t + 2 < T_DIM) h1 = Hrow[(size_t)(t + 2) * N_DIM + o];

        float acc = 0.f;
        for (int k = 0; k < K; k++) acc += g_M[(size_t)sidx[k] * N_DIM + o];

        mem = mem * beta + h * omb + acc;
        float s = (mem * inv_n - bth > 0.f) ? 1.f : 0.f;
        Orow[(size_t)t * N_DIM + o] = s;

        unsigned bal = __ballot_sync(0xffffffffu, s > 0.f);
        if (lane == 0) warp_cnt[warp] = __popc(bal);
        __syncthreads();                     // sidx reads done + warp_cnt visible
        if (warp == 0) {
            int v = warp_cnt[lane];
            int x = v;
#pragma unroll
            for (int d = 1; d < 32; d <<= 1) {
                int y = __shfl_up_sync(0xffffffffu, x, d);
                if (lane >= d) x += y;
            }
            warp_off[lane] = x - v;          // exclusive prefix
            if (lane == 31) {
                scnt = x;
                if (x > 0) atomicAdd(&g_cnt[t], x);
            }
        }
        __syncthreads();                     // offsets visible; sidx writable
        if (s > 0.f)
            sidx[warp_off[warp] + __popc(bal & ((1u << lane) - 1u))] = o;
        K = scnt;
        __syncthreads();                     // sidx visible for next gather
    }
}

__global__ void finalize_kernel(float* __restrict__ out, int out_size) {
    if (threadIdx.x == 0 && out_size >= NTOT + 2) {
        int sum = 0, mx = 0;
        for (int t = 0; t < T_DIM; t++) {
            sum += g_cnt[t];
            mx = max(mx, g_cnt[t]);
        }
        out[NTOT]     = 0.5f * (float)sum / (float)NTOT;
        out[NTOT + 1] = (float)mx / (float)(B_DIM * N_DIM);
    }
}

// ---------------------------------------------------------------------------
extern "C" void kernel_launch(void* const* d_in, const int* in_sizes, int n_in,
                              void* d_out, int out_size) {
    const float* x    = (const float*)d_in[0];
    const float* w    = (const float*)d_in[1];
    const float* v    = (const float*)d_in[2];
    const float* beta = (const float*)d_in[3];
    const float* bvec = (const float*)d_in[4];
    float* out = (float*)d_out;

    cudaFuncSetAttribute(gemm_h_tc_kernel,
                         cudaFuncAttributeMaxDynamicSharedMemorySize, SMEM_BYTES);
    cudaFuncSetAttribute(gemm_dM_tc_kernel,
                         cudaFuncAttributeMaxDynamicSharedMemorySize, SMEM_BYTES);

    zero_cnt_kernel<<<1, 128>>>();
    norm_kernel<<<N_DIM / 256, 256>>>(w);
    convert_x_kernel<<<NTOT / 4 / 256, 256>>>(x);
    convert_wt_kernel<<<dim3(N_DIM / 32, N_DIM / 32), dim3(32, 32)>>>(w);
    gemm_dM_tc_kernel<<<dim3(N_DIM / 128, N_DIM / 128), 256, SMEM_BYTES>>>(v, beta);
    gemm_h_tc_kernel<<<dim3(N_DIM / 128, MT / 128), 256, SMEM_BYTES>>>();
    scan_kernel<<<B_DIM, 1024>>>(bvec, beta, out);
    finalize_kernel<<<1, 32>>>(out, out_size);
}